// round 4
// baseline (speedup 1.0000x reference)
#include <cuda_runtime.h>
#include <cuda_fp16.h>
#include <cstdint>

// ---------------------------------------------------------------------------
// Problem constants
// ---------------------------------------------------------------------------
#define M_TOK   64
#define KDIM    8192
#define NOUT    14336
#define KW      (KDIM / 2)          // 4096 int32 per output row
#define NTILE   128
#define GRID_N  (NOUT / NTILE)      // 112 CTAs = one wave

// x (fp16, k-permuted + bank-swizzled) staged per 64-k chunk: 128 chunks x 8KB
__device__ __align__(16) unsigned char g_ximg[(size_t)M_TOK * KDIM * 2];  // 1 MB

// ---------------------------------------------------------------------------
// Helpers
// ---------------------------------------------------------------------------
__device__ __forceinline__ void cp16(uint32_t saddr, const void* g) {
    asm volatile("cp.async.cg.shared.global [%0], [%1], 16;" :: "r"(saddr), "l"(g));
}
__device__ __forceinline__ void cp_commit() {
    asm volatile("cp.async.commit_group;" ::: "memory");
}
__device__ __forceinline__ uint2 lds64(uint32_t addr) {
    uint2 r;
    asm volatile("ld.shared.v2.u32 {%0,%1}, [%2];" : "=r"(r.x), "=r"(r.y) : "r"(addr));
    return r;
}
__device__ __forceinline__ void mma16816(float* d, uint32_t a0, uint32_t a1,
                                         uint32_t a2, uint32_t a3,
                                         uint32_t b0, uint32_t b1) {
    asm volatile(
        "mma.sync.aligned.m16n8k16.row.col.f32.f16.f16.f32 "
        "{%0,%1,%2,%3}, {%4,%5,%6,%7}, {%8,%9}, {%0,%1,%2,%3};"
        : "+f"(d[0]), "+f"(d[1]), "+f"(d[2]), "+f"(d[3])
        : "r"(a0), "r"(a1), "r"(a2), "r"(a3), "r"(b0), "r"(b1));
}

// int4-pair dequant: one int32 (value 0..255; lo nibble = even k) -> f16x2 {qlo,qhi}.
// lo half = 0x6408 ^ nibLo = 1032 + qlo (exact); HSUB2 by 1032 -> exact signed int4.
__device__ __forceinline__ uint32_t dq2(uint32_t v) {
    uint32_t t = (v & 0xFu) ^ 0x64086408u;
    uint32_t p = t ^ ((v << 12) & 0x000F0000u);
    __half2 hp = *reinterpret_cast<__half2*>(&p);
    __half2 r = __hsub2(hp, __half2half2(__ushort_as_half((unsigned short)0x6408)));
    return *reinterpret_cast<uint32_t*>(&r);
}

// ---------------------------------------------------------------------------
// Pre-kernel: x [64,8192] f32 -> f16 with the k-permutation + LDS swizzle baked in.
// Chunk cc covers physical k [cc*64, cc*64+64). Granule q (q = 4c+s, c=q>>2, s=q&3)
// stores 4 halves = physical k {8c+2s, 8c+2s+1, 32+8c+2s, 33+8c+2s} at byte offset
// tok*128 + ((q ^ (tok&7)) * 8) inside the 8KB chunk tile.
// ---------------------------------------------------------------------------
__global__ void convert_x(const float* __restrict__ x) {
    int tg  = blockIdx.x * 256 + threadIdx.x;    // 131072 threads
    int cc  = tg >> 10;
    int rem = tg & 1023;
    int tok = rem >> 4;
    int q   = rem & 15;
    int c = q >> 2, s = q & 3;
    int k0 = cc * 64 + 8 * c + 2 * s;
    float2 v0 = *reinterpret_cast<const float2*>(x + (size_t)tok * KDIM + k0);
    float2 v1 = *reinterpret_cast<const float2*>(x + (size_t)tok * KDIM + k0 + 32);
    __half2 h0 = __floats2half2_rn(v0.x, v0.y);
    __half2 h1 = __floats2half2_rn(v1.x, v1.y);
    uint2 st;
    st.x = *reinterpret_cast<uint32_t*>(&h0);
    st.y = *reinterpret_cast<uint32_t*>(&h1);
    *reinterpret_cast<uint2*>(g_ximg + (size_t)cc * 8192 + tok * 128 +
                              ((q ^ (tok & 7)) << 3)) = st;
}

// ---------------------------------------------------------------------------
// Main kernel: CTA = 128 out-rows x 64 tokens. 8 warps in a 4(row) x 2(token) grid;
// warp tile = 32 rows x 32 tokens. K loop: 64 outer iters x 128 k (2 halves of 64 k).
// Weights: gmem -> registers -> dq2 -> A fragments. x: cp.async 2-stage SMEM ring.
// ---------------------------------------------------------------------------
__global__ __launch_bounds__(256, 1)
void qmain(const int* __restrict__ wp, const float* __restrict__ ws,
           const float* __restrict__ bias, float* __restrict__ out) {
    __shared__ __align__(16) unsigned char sB[2][16384];

    const int tid  = threadIdx.x;
    const int lane = tid & 31, warp = tid >> 5;
    const int wr = warp >> 1, wt = warp & 1;
    const int rl = lane >> 2, cl = lane & 3;
    const int r0 = blockIdx.x * NTILE;

    const uint32_t sb = (uint32_t)__cvta_generic_to_shared(&sB[0][0]);

    // weight row pointers [mt][rh]; each thread owns int32s 4*cl.. within a row
    const int* wptr[2][2];
#pragma unroll
    for (int mt = 0; mt < 2; mt++)
#pragma unroll
        for (int rh = 0; rh < 2; rh++)
            wptr[mt][rh] = wp + (size_t)(r0 + wr * 32 + mt * 16 + rh * 8 + rl) * KW + 4 * cl;

    // B-fragment smem addresses: token = wt*32 + nt*8 + rl; granule (4*cl+s)^rl
    uint32_t baddr[4];
#pragma unroll
    for (int nt = 0; nt < 4; nt++)
        baddr[nt] = sb + (uint32_t)(wt * 32 + nt * 8 + rl) * 128;
    uint32_t gq[4];
#pragma unroll
    for (int s = 0; s < 4; s++)
        gq[s] = (uint32_t)(((4 * cl + s) ^ rl) << 3);

#define LOADW(W, it_, half_) do {                                               \
        _Pragma("unroll")                                                       \
        for (int mt_ = 0; mt_ < 2; mt_++) {                                     \
            _Pragma("unroll")                                                   \
            for (int rh_ = 0; rh_ < 2; rh_++) {                                 \
                const int* p_ = wptr[mt_][rh_] + (it_) * 64 + (half_) * 32;     \
                W[mt_][rh_][0] = *reinterpret_cast<const uint4*>(p_);           \
                W[mt_][rh_][1] = *reinterpret_cast<const uint4*>(p_ + 16);      \
            }                                                                   \
        } } while (0)

#define COMP4(u4, s_) ((s_) == 0 ? (u4).x : (s_) == 1 ? (u4).y : (s_) == 2 ? (u4).z : (u4).w)

#define COMPUTE(W, soff_) do {                                                  \
        _Pragma("unroll")                                                       \
        for (int s_ = 0; s_ < 4; s_++) {                                        \
            uint32_t a00 = dq2(COMP4(W[0][0][0], s_));                          \
            uint32_t a01 = dq2(COMP4(W[0][1][0], s_));                          \
            uint32_t a02 = dq2(COMP4(W[0][0][1], s_));                          \
            uint32_t a03 = dq2(COMP4(W[0][1][1], s_));                          \
            uint32_t a10 = dq2(COMP4(W[1][0][0], s_));                          \
            uint32_t a11 = dq2(COMP4(W[1][1][0], s_));                          \
            uint32_t a12 = dq2(COMP4(W[1][0][1], s_));                          \
            uint32_t a13 = dq2(COMP4(W[1][1][1], s_));                          \
            _Pragma("unroll")                                                   \
            for (int nt_ = 0; nt_ < 4; nt_++) {                                 \
                uint2 b_ = lds64(baddr[nt_] + (soff_) + gq[s_]);                \
                mma16816(d[0][nt_], a00, a01, a02, a03, b_.x, b_.y);            \
                mma16816(d[1][nt_], a10, a11, a12, a13, b_.x, b_.y);            \
            }                                                                   \
        } } while (0)

    uint4 wA[2][2][2], wB[2][2][2];
    float d[2][4][4] = {};

    // Prologue: weights for (it=0, half=0); cp.async stages 0 and 1
    LOADW(wA, 0, 0);
#pragma unroll
    for (int j = 0; j < 4; j++)
        cp16(sb + tid * 64 + j * 16, g_ximg + tid * 64 + j * 16);
    cp_commit();
#pragma unroll
    for (int j = 0; j < 4; j++)
        cp16(sb + 16384 + tid * 64 + j * 16, g_ximg + 16384 + tid * 64 + j * 16);
    cp_commit();

    for (int it = 0; it < 64; it++) {
        asm volatile("cp.async.wait_group 1;" ::: "memory");
        __syncthreads();
        const uint32_t soff = (uint32_t)(it & 1) * 16384u;

        // half 0: compute from wA, prefetch wB (this iter's half 1)
        LOADW(wB, it, 1);
        COMPUTE(wA, soff);

        // half 1: compute from wB, prefetch wA (next iter's half 0)
        if (it < 63) LOADW(wA, it + 1, 0);
        COMPUTE(wB, soff + 8192u);

        __syncthreads();
        if (it + 2 < 64) {
            const unsigned char* src = g_ximg + (size_t)(it + 2) * 16384;
#pragma unroll
            for (int j = 0; j < 4; j++)
                cp16(sb + soff + tid * 64 + j * 16, src + tid * 64 + j * 16);
        }
        cp_commit();   // always commit: keeps group numbering uniform for wait_group 1
    }

    // Epilogue: scale + bias, scattered-but-sector-full STG.32
    float sc[2][2], bi[2][2];
#pragma unroll
    for (int mt = 0; mt < 2; mt++)
#pragma unroll
        for (int rh = 0; rh < 2; rh++) {
            int R = r0 + wr * 32 + mt * 16 + rh * 8 + rl;
            sc[mt][rh] = ws[R];
            bi[mt][rh] = bias[R];
        }
#pragma unroll
    for (int mt = 0; mt < 2; mt++) {
        const int Rb = r0 + wr * 32 + mt * 16 + rl;
#pragma unroll
        for (int nt = 0; nt < 4; nt++) {
            const int T = wt * 32 + nt * 8 + 2 * cl;
            out[(size_t)T * NOUT + Rb]           = d[mt][nt][0] * sc[mt][0] + bi[mt][0];
            out[(size_t)(T + 1) * NOUT + Rb]     = d[mt][nt][1] * sc[mt][0] + bi[mt][0];
            out[(size_t)T * NOUT + Rb + 8]       = d[mt][nt][2] * sc[mt][1] + bi[mt][1];
            out[(size_t)(T + 1) * NOUT + Rb + 8] = d[mt][nt][3] * sc[mt][1] + bi[mt][1];
        }
    }
}

// ---------------------------------------------------------------------------
extern "C" void kernel_launch(void* const* d_in, const int* in_sizes, int n_in,
                              void* d_out, int out_size) {
    (void)in_sizes; (void)n_in; (void)out_size;
    const float* x    = (const float*)d_in[0];
    const int*   wpk  = (const int*)d_in[1];
    const float* wsc  = (const float*)d_in[2];
    const float* bias = (const float*)d_in[3];
    float* out = (float*)d_out;

    convert_x<<<512, 256>>>(x);                       // 131072 threads
    qmain<<<GRID_N, 256>>>(wpk, wsc, bias, out);      // 112 CTAs, one wave
}